// round 14
// baseline (speedup 1.0000x reference)
#include <cuda_runtime.h>
#include <cuda_bf16.h>
#include <math.h>
#include <stdint.h>

// Problem constants
#define BATCH   2
#define SEQ     2048
#define DMODEL  1024
#define NHEADS  16
#define DHEAD   64
#define MROWS   (BATCH * SEQ)          // 4096
#define QKVN    (3 * DMODEL)           // 3072

// K-permutation within each 8-element group: stored[j] = natural[pi(j)],
// pi = [0,4,1,5,2,6,3,7]; sigma = pi^-1 = [0,2,4,6,1,3,5,7].
__device__ float g_qkv[(size_t)MROWS * QKVN];     // head-dim permuted
__device__ float g_att[(size_t)MROWS * DMODEL];   // permuted (== GEMM3 A layout)
__device__ float g_xr [(size_t)MROWS * DMODEL];   // permuted
__device__ float g_wir[(size_t)QKVN * DMODEL];    // permuted
__device__ float g_wor[(size_t)DMODEL * DMODEL];  // permuted

// ---------------------------------------------------------------------------
// helpers
// ---------------------------------------------------------------------------
__device__ __forceinline__ unsigned f2tf(float f) {
    unsigned r;
    asm("cvt.rna.tf32.f32 %0, %1;" : "=r"(r) : "f"(f));
    return r;
}
__device__ __forceinline__ float roundtf(float f) {
    return __uint_as_float(f2tf(f));
}
__device__ __forceinline__ void cp16(void* sdst, const void* gsrc) {
    unsigned s = (unsigned)__cvta_generic_to_shared(sdst);
    asm volatile("cp.async.cg.shared.global [%0], [%1], 16;" :: "r"(s), "l"(gsrc) : "memory");
}
#define CP_COMMIT()  asm volatile("cp.async.commit_group;" ::: "memory")
#define CP_WAIT0()   asm volatile("cp.async.wait_group 0;" ::: "memory")
#define CP_WAIT1()   asm volatile("cp.async.wait_group 1;" ::: "memory")

__device__ __forceinline__ void mma8(float c[4],
    unsigned a0, unsigned a1, unsigned a2, unsigned a3,
    unsigned b0, unsigned b1)
{
    asm volatile(
        "mma.sync.aligned.m16n8k8.row.col.f32.tf32.tf32.f32 "
        "{%0,%1,%2,%3}, {%4,%5,%6,%7}, {%8,%9}, {%0,%1,%2,%3};"
        : "+f"(c[0]), "+f"(c[1]), "+f"(c[2]), "+f"(c[3])
        : "r"(a0), "r"(a1), "r"(a2), "r"(a3), "r"(b0), "r"(b1));
}

// ---------------------------------------------------------------------------
// Pre-pass: round (unbiased rna) + k-permute (out[j] = in[pi(j)] per 8-group)
// ---------------------------------------------------------------------------
__global__ void round_perm_k(const float* __restrict__ s, float* __restrict__ d, int n8)
{
    int i = blockIdx.x * blockDim.x + threadIdx.x;
    if (i < n8) {
        const float4* s4 = (const float4*)s + (size_t)i * 2;
        float4 i0 = s4[0], i1 = s4[1];
        float4 o0 = { roundtf(i0.x), roundtf(i1.x), roundtf(i0.y), roundtf(i1.y) };
        float4 o1 = { roundtf(i0.z), roundtf(i1.z), roundtf(i0.w), roundtf(i1.w) };
        float4* d4 = (float4*)d + (size_t)i * 2;
        d4[0] = o0; d4[1] = o1;
    }
}

// ---------------------------------------------------------------------------
// GEMM (NT) tf32: C[M,N] = A[M,K] @ B[N,K]^T + bias[N]
// A,B K-permuted. MODE=1: round + sigma-permute output cols (qkv).
// 128x128 block, BK=16, 128 threads (4 warps, 64x64 each).
// 2-STAGE cp.async pipeline (49.2 KB) so 3 CTAs co-reside (147 KB, regs 168).
// Issue-after-sync ordering (safe: prior readers passed the barrier).
// ---------------------------------------------------------------------------
#define GROW 24                  // floats per smem row
#define GSTG (128 * GROW)        // floats per stage per matrix (3072)
#define GEMM_SMEM (4 * GSTG * 4) // 49152 bytes (2 stages x A,B)

template<int MODE>
__global__ __launch_bounds__(128, 3) void gemm_tf32(
    const float* __restrict__ A, const float* __restrict__ B,
    const float* __restrict__ bias, float* __restrict__ C,
    int M, int N, int K)
{
    extern __shared__ __align__(16) float sm[];
    float* As = sm;              // [2][128][24]
    float* Bs = sm + 2 * GSTG;   // [2][128][24]

    const int tid  = threadIdx.x;
    const int warp = tid >> 5;
    const int lane = tid & 31;
    const int g    = lane >> 2;
    const int tg   = lane & 3;
    const int wm   = warp >> 1;
    const int wn   = warp & 1;

    const int m0 = blockIdx.y * 128;
    const int n0 = blockIdx.x * 128;

    float acc[4][8][4];
#pragma unroll
    for (int i = 0; i < 4; i++)
#pragma unroll
        for (int j = 0; j < 8; j++)
#pragma unroll
            for (int r = 0; r < 4; r++) acc[i][j][r] = 0.f;

    const int iters = K >> 4;

#define GEMM_ISSUE(st, k0)                                                     \
    {                                                                          \
        _Pragma("unroll")                                                      \
        for (int i = 0; i < 4; i++) {                                          \
            int f  = i * 128 + tid;                                            \
            int r  = f >> 2;                                                   \
            int c4 = (f & 3) << 2;                                             \
            cp16(&As[(st) * GSTG + r * GROW + c4],                             \
                 &A[(size_t)(m0 + r) * K + (k0) + c4]);                        \
            cp16(&Bs[(st) * GSTG + r * GROW + c4],                             \
                 &B[(size_t)(n0 + r) * K + (k0) + c4]);                        \
        }                                                                      \
        CP_COMMIT();                                                           \
    }

    GEMM_ISSUE(0, 0)

    for (int it = 0; it < iters; it++) {
        const int buf = it & 1;
        CP_WAIT0();        // stage it complete (overlapped with compute it-1)
        __syncthreads();   // all threads past compute(it-1): buf^1 reusable

        if (it + 1 < iters) {
            GEMM_ISSUE(buf ^ 1, (it + 1) << 4)   // overlaps compute(it)
        }

        const float2* A2 = (const float2*)(As + buf * GSTG);
        const float2* B2 = (const float2*)(Bs + buf * GSTG);
#pragma unroll
        for (int ks = 0; ks < 2; ks++) {
            const int kk2 = ks * 4;
            unsigned a[4][4];
#pragma unroll
            for (int ma = 0; ma < 4; ma++) {
                int r = wm * 64 + ma * 16 + g;
                float2 p = A2[r * 12 + kk2 + tg];       // (a0, a2)
                float2 q = A2[r * 12 + 96 + kk2 + tg];  // row+8  (a1, a3)
                a[ma][0] = __float_as_uint(p.x);
                a[ma][1] = __float_as_uint(q.x);
                a[ma][2] = __float_as_uint(p.y);
                a[ma][3] = __float_as_uint(q.y);
            }
            unsigned b[8][2];
#pragma unroll
            for (int na = 0; na < 8; na++) {
                int n = wn * 64 + na * 8 + g;
                float2 bb = B2[n * 12 + kk2 + tg];      // (b0, b1)
                b[na][0] = __float_as_uint(bb.x);
                b[na][1] = __float_as_uint(bb.y);
            }
#pragma unroll
            for (int ma = 0; ma < 4; ma++)
#pragma unroll
                for (int na = 0; na < 8; na++)
                    mma8(acc[ma][na], a[ma][0], a[ma][1], a[ma][2], a[ma][3],
                         b[na][0], b[na][1]);
        }
    }

    // Epilogue (compile-time split).
    const int pe0 = (tg < 2) ? tg * 4     : tg * 4 - 7;   // sigma(2tg)
    const int pe1 = (tg < 2) ? tg * 4 + 2 : tg * 4 - 5;   // sigma(2tg+1)
#pragma unroll
    for (int ma = 0; ma < 4; ma++) {
        int row0 = m0 + wm * 64 + ma * 16 + g;
#pragma unroll
        for (int na = 0; na < 8; na++) {
            int colb = n0 + wn * 64 + na * 8;
            float2 bv = *(const float2*)&bias[colb + tg * 2];
            float v00 = acc[ma][na][0] + bv.x, v01 = acc[ma][na][1] + bv.y;
            float v10 = acc[ma][na][2] + bv.x, v11 = acc[ma][na][3] + bv.y;
            if (MODE) {   // rounded + sigma-permuted scatter (qkv)
                float* r0 = &C[(size_t)row0 * N + colb];
                float* r1 = &C[(size_t)(row0 + 8) * N + colb];
                r0[pe0] = roundtf(v00); r0[pe1] = roundtf(v01);
                r1[pe0] = roundtf(v10); r1[pe1] = roundtf(v11);
            } else {      // natural vectorized (final output)
                *(float2*)&C[(size_t)row0 * N + colb + tg * 2]
                    = make_float2(v00, v01);
                *(float2*)&C[(size_t)(row0 + 8) * N + colb + tg * 2]
                    = make_float2(v10, v11);
            }
        }
    }
}

// ---------------------------------------------------------------------------
// Flash attention, tf32, head-dim-permuted qkv (PROVEN R12, unchanged).
// Grid: (S/64, B*H). Block: 128. BQ=64, BK=32 dbuf cp.async.
// ---------------------------------------------------------------------------
#define OFF_K   0
#define OFF_V   4608
#define OFF_P   9216
#define SM_FLT  11776        // 47104 bytes

__global__ __launch_bounds__(128) void attn_tf32(
    const float* __restrict__ qkv, float* __restrict__ outp)
{
    __shared__ __align__(16) float smf[SM_FLT];

    const int tid  = threadIdx.x;
    const int warp = tid >> 5;
    const int lane = tid & 31;
    const int g    = lane >> 2;
    const int tg   = lane & 3;
    const int wq0  = warp * 16;

    const int qt = blockIdx.x;
    const int bh = blockIdx.y;
    const int b  = bh >> 4;
    const int h  = bh & 15;

    const size_t rowbase = (size_t)b * SEQ * QKVN;
    const int qcol = h * DHEAD;
    const int kcol = DMODEL + h * DHEAD;
    const int vcol = 2 * DMODEL + h * DHEAD;
    const int q0   = qt * 64;

#pragma unroll
    for (int i = 0; i < 8; i++) {
        int f  = i * 128 + tid;
        int r  = f >> 4;
        int c4 = (f & 15) << 2;
        cp16(&smf[r * 72 + c4],
             &qkv[rowbase + (size_t)(q0 + r) * QKVN + qcol + c4]);
    }
    CP_COMMIT();
    CP_WAIT0();
    __syncthreads();

    unsigned qa[8][4];
    {
        const float2* Q2 = (const float2*)smf;
#pragma unroll
        for (int ks = 0; ks < 8; ks++) {
            float2 p = Q2[(wq0 + g    ) * 36 + ks * 4 + tg];
            float2 q = Q2[(wq0 + g + 8) * 36 + ks * 4 + tg];
            qa[ks][0] = __float_as_uint(p.x);
            qa[ks][1] = __float_as_uint(q.x);
            qa[ks][2] = __float_as_uint(p.y);
            qa[ks][3] = __float_as_uint(q.y);
        }
    }
    __syncthreads();

    float o[8][4];
#pragma unroll
    for (int i = 0; i < 8; i++)
#pragma unroll
        for (int j = 0; j < 4; j++) o[i][j] = 0.f;
    float mx0 = -INFINITY, mx1 = -INFINITY;
    float l0 = 0.f, l1 = 0.f;

    const int pe0 = (tg < 2) ? tg * 4     : tg * 4 - 7;
    const int pe1 = (tg < 2) ? tg * 4 + 2 : tg * 4 - 5;

#define ATT_ISSUE(nb, k0g)                                                     \
    {                                                                          \
        _Pragma("unroll")                                                      \
        for (int i = 0; i < 4; i++) {                                          \
            int f  = i * 128 + tid;                                            \
            int r  = f >> 4;                                                   \
            int c4 = (f & 15) << 2;                                            \
            cp16(&smf[OFF_K + (nb) * 2304 + r * 72 + c4],                      \
                 &qkv[rowbase + (size_t)((k0g) + r) * QKVN + kcol + c4]);      \
            cp16(&smf[OFF_V + (nb) * 2304 + r * 72 + c4],                      \
                 &qkv[rowbase + (size_t)((k0g) + r) * QKVN + vcol + c4]);      \
        }                                                                      \
        CP_COMMIT();                                                           \
    }

    ATT_ISSUE(0, 0)

    const int NT = SEQ / 32;
    for (int t = 0; t < NT; t++) {
        const int buf = t & 1;

        if (t + 1 < NT) {
            ATT_ISSUE(buf ^ 1, (t + 1) * 32)
            CP_WAIT1();
        } else {
            CP_WAIT0();
        }
        __syncthreads();

        const float2* K2 = (const float2*)(smf + OFF_K + buf * 2304);
        const float*  Vs = smf + OFF_V + buf * 2304;

        float s[4][4];
#pragma unroll
        for (int na = 0; na < 4; na++)
#pragma unroll
            for (int r = 0; r < 4; r++) s[na][r] = 0.f;

#pragma unroll
        for (int ks = 0; ks < 8; ks++) {
            const int kk2 = ks * 4;
#pragma unroll
            for (int na = 0; na < 4; na++) {
                float2 bb = K2[(na * 8 + g) * 36 + kk2 + tg];
                mma8(s[na], qa[ks][0], qa[ks][1], qa[ks][2], qa[ks][3],
                     __float_as_uint(bb.x), __float_as_uint(bb.y));
            }
        }

        float t0 = -INFINITY, t1 = -INFINITY;
#pragma unroll
        for (int na = 0; na < 4; na++) {
            s[na][0] *= 0.125f; s[na][1] *= 0.125f;
            s[na][2] *= 0.125f; s[na][3] *= 0.125f;
            t0 = fmaxf(t0, fmaxf(s[na][0], s[na][1]));
            t1 = fmaxf(t1, fmaxf(s[na][2], s[na][3]));
        }
        t0 = fmaxf(t0, __shfl_xor_sync(0xffffffffu, t0, 1));
        t0 = fmaxf(t0, __shfl_xor_sync(0xffffffffu, t0, 2));
        t1 = fmaxf(t1, __shfl_xor_sync(0xffffffffu, t1, 1));
        t1 = fmaxf(t1, __shfl_xor_sync(0xffffffffu, t1, 2));

        float mn0 = fmaxf(mx0, t0), mn1 = fmaxf(mx1, t1);
        float corr0 = __expf(mx0 - mn0), corr1 = __expf(mx1 - mn1);

        float ls0 = 0.f, ls1 = 0.f;
        {
            float* Pr0 = smf + OFF_P + (wq0 + g    ) * 40;
            float* Pr1 = smf + OFF_P + (wq0 + g + 8) * 40;
#pragma unroll
            for (int na = 0; na < 4; na++) {
                float p0 = __expf(s[na][0] - mn0);
                float p1 = __expf(s[na][1] - mn0);
                float p2 = __expf(s[na][2] - mn1);
                float p3 = __expf(s[na][3] - mn1);
                ls0 += p0 + p1; ls1 += p2 + p3;
                int cb = na * 8;
                Pr0[cb + pe0] = roundtf(p0); Pr0[cb + pe1] = roundtf(p1);
                Pr1[cb + pe0] = roundtf(p2); Pr1[cb + pe1] = roundtf(p3);
            }
        }
        ls0 += __shfl_xor_sync(0xffffffffu, ls0, 1);
        ls0 += __shfl_xor_sync(0xffffffffu, ls0, 2);
        ls1 += __shfl_xor_sync(0xffffffffu, ls1, 1);
        ls1 += __shfl_xor_sync(0xffffffffu, ls1, 2);
        l0 = l0 * corr0 + ls0;  mx0 = mn0;
        l1 = l1 * corr1 + ls1;  mx1 = mn1;

#pragma unroll
        for (int na = 0; na < 8; na++) {
            o[na][0] *= corr0; o[na][1] *= corr0;
            o[na][2] *= corr1; o[na][3] *= corr1;
        }

        __syncwarp();

        {
            const float2* P2 = (const float2*)(smf + OFF_P);
#pragma unroll
            for (int ks = 0; ks < 4; ks++) {
                const int kk = ks * 8;
                float2 pa = P2[(wq0 + g    ) * 20 + ks * 4 + tg];
                float2 pb = P2[(wq0 + g + 8) * 20 + ks * 4 + tg];
                unsigned a0 = __float_as_uint(pa.x);
                unsigned a1 = __float_as_uint(pb.x);
                unsigned a2 = __float_as_uint(pa.y);
                unsigned a3 = __float_as_uint(pb.y);
#pragma unroll
                for (int na = 0; na < 8; na++) {
                    int n = na * 8 + g;
                    unsigned b0 = __float_as_uint(Vs[(kk + tg    ) * 72 + n]);
                    unsigned b1 = __float_as_uint(Vs[(kk + tg + 4) * 72 + n]);
                    mma8(o[na], a0, a1, a2, a3, b0, b1);
                }
            }
        }
        __syncthreads();
    }

    float inv0 = 1.0f / l0, inv1 = 1.0f / l1;
    int row0 = q0 + wq0 + g;
    size_t base0 = ((size_t)bh * SEQ + row0)     * DHEAD;
    size_t base1 = ((size_t)bh * SEQ + row0 + 8) * DHEAD;
#pragma unroll
    for (int na = 0; na < 8; na++) {
        int c = na * 8 + tg * 2;
        float2 v0 = { roundtf(o[na][0] * inv0), roundtf(o[na][1] * inv0) };
        float2 v1 = { roundtf(o[na][2] * inv1), roundtf(o[na][3] * inv1) };
        *(float2*)&outp[base0 + c] = v0;
        *(float2*)&outp[base1 + c] = v1;
    }
}

// ---------------------------------------------------------------------------
// Launch
// ---------------------------------------------------------------------------
extern "C" void kernel_launch(void* const* d_in, const int* in_sizes, int n_in,
                              void* d_out, int out_size)
{
    const float* x     = (const float*)d_in[0];
    const float* w_in  = (const float*)d_in[1];
    const float* b_in  = (const float*)d_in[2];
    const float* w_out = (const float*)d_in[3];
    const float* b_out = (const float*)d_in[4];
    float* out = (float*)d_out;

    float *qkv_p, *att_p, *xr_p, *wir_p, *wor_p;
    cudaGetSymbolAddress((void**)&qkv_p, g_qkv);
    cudaGetSymbolAddress((void**)&att_p, g_att);
    cudaGetSymbolAddress((void**)&xr_p,  g_xr);
    cudaGetSymbolAddress((void**)&wir_p, g_wir);
    cudaGetSymbolAddress((void**)&wor_p, g_wor);

    cudaFuncSetAttribute(gemm_tf32<1>,
        cudaFuncAttributeMaxDynamicSharedMemorySize, GEMM_SMEM);
    cudaFuncSetAttribute(gemm_tf32<0>,
        cudaFuncAttributeMaxDynamicSharedMemorySize, GEMM_SMEM);
    cudaFuncSetAttribute(gemm_tf32<1>,
        cudaFuncAttributePreferredSharedMemoryCarveout, 100);
    cudaFuncSetAttribute(gemm_tf32<0>,
        cudaFuncAttributePreferredSharedMemoryCarveout, 100);

    // 0) Round + k-permute inputs
    {
        int n8x  = (MROWS * DMODEL) / 8;
        int n8wi = (QKVN * DMODEL) / 8;
        int n8wo = (DMODEL * DMODEL) / 8;
        round_perm_k<<<(n8x  + 255) / 256, 256>>>(x,     xr_p,  n8x);
        round_perm_k<<<(n8wi + 255) / 256, 256>>>(w_in,  wir_p, n8wi);
        round_perm_k<<<(n8wo + 255) / 256, 256>>>(w_out, wor_p, n8wo);
    }
    // 1) QKV = x @ w_in^T + b_in  (MODE=1: rounded + sigma-permuted columns)
    {
        dim3 grid(QKVN / 128, MROWS / 128);
        gemm_tf32<1><<<grid, 128, GEMM_SMEM>>>(xr_p, wir_p, b_in, qkv_p,
                                               MROWS, QKVN, DMODEL);
    }
    // 2) attention (permuted-dim qkv) -> g_att (permuted) in [B][H][S][Dh]
    {
        dim3 grid(SEQ / 64, BATCH * NHEADS);
        attn_tf32<<<grid, 128>>>(qkv_p, att_p);
    }
    // 3) out = att @ w_out^T + b_out (MODE=0: natural fp32 output)
    {
        dim3 grid(DMODEL / 128, MROWS / 128);
        gemm_tf32<0><<<grid, 128, GEMM_SMEM>>>(att_p, wor_p, b_out, out,
                                               MROWS, DMODEL, DMODEL);
    }
}

// round 15
// speedup vs baseline: 1.1084x; 1.1084x over previous
#include <cuda_runtime.h>
#include <cuda_bf16.h>
#include <math.h>
#include <stdint.h>

// Problem constants
#define BATCH   2
#define SEQ     2048
#define DMODEL  1024
#define NHEADS  16
#define DHEAD   64
#define MROWS   (BATCH * SEQ)          // 4096
#define QKVN    (3 * DMODEL)           // 3072

// K-permutation within each 8-element group: stored[j] = natural[pi(j)],
// pi = [0,4,1,5,2,6,3,7]; sigma = pi^-1 = [0,2,4,6,1,3,5,7].
__device__ float g_qkv[(size_t)MROWS * QKVN];     // head-dim permuted
__device__ float g_att[(size_t)MROWS * DMODEL];   // permuted (== GEMM3 A layout)
__device__ float g_xr [(size_t)MROWS * DMODEL];   // permuted
__device__ float g_wir[(size_t)QKVN * DMODEL];    // permuted
__device__ float g_wor[(size_t)DMODEL * DMODEL];  // permuted

#define N8_X  ((MROWS * DMODEL) / 8)          // 524288
#define N8_WI ((QKVN * DMODEL) / 8)           // 393216
#define N8_WO ((DMODEL * DMODEL) / 8)         // 131072
#define N8_TOT (N8_X + N8_WI + N8_WO)         // 1048576

// ---------------------------------------------------------------------------
// helpers
// ---------------------------------------------------------------------------
__device__ __forceinline__ unsigned f2tf(float f) {
    unsigned r;
    asm("cvt.rna.tf32.f32 %0, %1;" : "=r"(r) : "f"(f));
    return r;
}
__device__ __forceinline__ float roundtf(float f) {
    return __uint_as_float(f2tf(f));
}
__device__ __forceinline__ void cp16(void* sdst, const void* gsrc) {
    unsigned s = (unsigned)__cvta_generic_to_shared(sdst);
    asm volatile("cp.async.cg.shared.global [%0], [%1], 16;" :: "r"(s), "l"(gsrc) : "memory");
}
#define CP_COMMIT()  asm volatile("cp.async.commit_group;" ::: "memory")
#define CP_WAIT0()   asm volatile("cp.async.wait_group 0;" ::: "memory")
#define CP_WAIT1()   asm volatile("cp.async.wait_group 1;" ::: "memory")

__device__ __forceinline__ void mma8(float c[4],
    unsigned a0, unsigned a1, unsigned a2, unsigned a3,
    unsigned b0, unsigned b1)
{
    asm volatile(
        "mma.sync.aligned.m16n8k8.row.col.f32.tf32.tf32.f32 "
        "{%0,%1,%2,%3}, {%4,%5,%6,%7}, {%8,%9}, {%0,%1,%2,%3};"
        : "+f"(c[0]), "+f"(c[1]), "+f"(c[2]), "+f"(c[3])
        : "r"(a0), "r"(a1), "r"(a2), "r"(a3), "r"(b0), "r"(b1));
}

// ---------------------------------------------------------------------------
// Fused pre-pass: round (unbiased rna) + k-permute for x, w_in, w_out.
// One thread per 8-float group; branch selects tensor (coherent per block).
// ---------------------------------------------------------------------------
__global__ void round_perm_all(const float* __restrict__ x,
                               const float* __restrict__ wi,
                               const float* __restrict__ wo,
                               float* __restrict__ dx,
                               float* __restrict__ dwi,
                               float* __restrict__ dwo)
{
    int i = blockIdx.x * blockDim.x + threadIdx.x;
    const float* s; float* d; int j;
    if (i < N8_X)               { s = x;  d = dx;  j = i; }
    else if (i < N8_X + N8_WI)  { s = wi; d = dwi; j = i - N8_X; }
    else if (i < N8_TOT)        { s = wo; d = dwo; j = i - N8_X - N8_WI; }
    else return;
    const float4* s4 = (const float4*)s + (size_t)j * 2;
    float4 i0 = s4[0], i1 = s4[1];
    float4 o0 = { roundtf(i0.x), roundtf(i1.x), roundtf(i0.y), roundtf(i1.y) };
    float4 o1 = { roundtf(i0.z), roundtf(i1.z), roundtf(i0.w), roundtf(i1.w) };
    float4* d4 = (float4*)d + (size_t)j * 2;
    d4[0] = o0; d4[1] = o1;
}

// ---------------------------------------------------------------------------
// GEMM (NT) tf32: C[M,N] = A[M,K] @ B[N,K]^T + bias[N]
// A,B K-permuted. MODE=1: rounded output, columns sigma-permuted via quad
// shfl-exchange -> all stores STG.64. MODE=0: natural vectorized output.
// 128x128 block, BK=16, 128 threads (4 warps, 64x64 each), 3-stage cp.async.
// ---------------------------------------------------------------------------
#define GROW 24                  // floats per smem row
#define GSTG (128 * GROW)        // floats per stage per matrix (3072)
#define GEMM_SMEM (6 * GSTG * 4) // 73728 bytes

template<int MODE>
__global__ __launch_bounds__(128) void gemm_tf32(
    const float* __restrict__ A, const float* __restrict__ B,
    const float* __restrict__ bias, float* __restrict__ C,
    int M, int N, int K)
{
    extern __shared__ __align__(16) float sm[];
    float* As = sm;              // [3][128][24]
    float* Bs = sm + 3 * GSTG;   // [3][128][24]

    const int tid  = threadIdx.x;
    const int warp = tid >> 5;
    const int lane = tid & 31;
    const int g    = lane >> 2;
    const int tg   = lane & 3;
    const int wm   = warp >> 1;
    const int wn   = warp & 1;

    const int m0 = blockIdx.y * 128;
    const int n0 = blockIdx.x * 128;

    float acc[4][8][4];
#pragma unroll
    for (int i = 0; i < 4; i++)
#pragma unroll
        for (int j = 0; j < 8; j++)
#pragma unroll
            for (int r = 0; r < 4; r++) acc[i][j][r] = 0.f;

    const int iters = K >> 4;

#define GEMM_ISSUE(st, k0)                                                     \
    {                                                                          \
        _Pragma("unroll")                                                      \
        for (int i = 0; i < 4; i++) {                                          \
            int f  = i * 128 + tid;                                            \
            int r  = f >> 2;                                                   \
            int c4 = (f & 3) << 2;                                             \
            cp16(&As[(st) * GSTG + r * GROW + c4],                             \
                 &A[(size_t)(m0 + r) * K + (k0) + c4]);                        \
            cp16(&Bs[(st) * GSTG + r * GROW + c4],                             \
                 &B[(size_t)(n0 + r) * K + (k0) + c4]);                        \
        }                                                                      \
        CP_COMMIT();                                                           \
    }

    GEMM_ISSUE(0, 0)
    if (iters > 1) GEMM_ISSUE(1, 16)

    int buf = 0;
    for (int it = 0; it < iters; it++) {
        if (it == iters - 1) { CP_WAIT0(); } else { CP_WAIT1(); }
        __syncthreads();

        if (it + 2 < iters) {
            int nst = buf + 2; if (nst >= 3) nst -= 3;
            GEMM_ISSUE(nst, (it + 2) << 4)
        }

        const float2* A2 = (const float2*)(As + buf * GSTG);
        const float2* B2 = (const float2*)(Bs + buf * GSTG);
#pragma unroll
        for (int ks = 0; ks < 2; ks++) {
            const int kk2 = ks * 4;
            unsigned a[4][4];
#pragma unroll
            for (int ma = 0; ma < 4; ma++) {
                int r = wm * 64 + ma * 16 + g;
                float2 p = A2[r * 12 + kk2 + tg];       // (a0, a2)
                float2 q = A2[r * 12 + 96 + kk2 + tg];  // row+8  (a1, a3)
                a[ma][0] = __float_as_uint(p.x);
                a[ma][1] = __float_as_uint(q.x);
                a[ma][2] = __float_as_uint(p.y);
                a[ma][3] = __float_as_uint(q.y);
            }
            unsigned b[8][2];
#pragma unroll
            for (int na = 0; na < 8; na++) {
                int n = wn * 64 + na * 8 + g;
                float2 bb = B2[n * 12 + kk2 + tg];      // (b0, b1)
                b[na][0] = __float_as_uint(bb.x);
                b[na][1] = __float_as_uint(bb.y);
            }
#pragma unroll
            for (int ma = 0; ma < 4; ma++)
#pragma unroll
                for (int na = 0; na < 8; na++)
                    mma8(acc[ma][na], a[ma][0], a[ma][1], a[ma][2], a[ma][3],
                         b[na][0], b[na][1]);
        }
        buf = (buf + 1 == 3) ? 0 : buf + 1;
    }

    // Epilogue.
    // MODE=1: quad shfl-exchange converts natural col pairs (2tg,2tg+1) into
    // sigma-adjacent pairs, stored as float2 at permuted quad offset
    // poff = ((tg&1)<<2) | (tg&2)  (tg0->0, tg2->2, tg1->4, tg3->6).
    const int poff = ((tg & 1) << 2) | (tg & 2);
    const bool lo = (tg < 2);
#pragma unroll
    for (int ma = 0; ma < 4; ma++) {
        int row0 = m0 + wm * 64 + ma * 16 + g;
#pragma unroll
        for (int na = 0; na < 8; na++) {
            int colb = n0 + wn * 64 + na * 8;
            float2 bv = *(const float2*)&bias[colb + tg * 2];
            float v00 = acc[ma][na][0] + bv.x, v01 = acc[ma][na][1] + bv.y;
            float v10 = acc[ma][na][2] + bv.x, v11 = acc[ma][na][3] + bv.y;
            if (MODE) {
                float s0 = lo ? v01 : v00;
                float s1 = lo ? v11 : v10;
                float o0 = __shfl_xor_sync(0xffffffffu, s0, 2);
                float o1 = __shfl_xor_sync(0xffffffffu, s1, 2);
                float2 w0 = lo ? make_float2(v00, o0) : make_float2(o0, v01);
                float2 w1 = lo ? make_float2(v10, o1) : make_float2(o1, v11);
                w0.x = roundtf(w0.x); w0.y = roundtf(w0.y);
                w1.x = roundtf(w1.x); w1.y = roundtf(w1.y);
                *(float2*)&C[(size_t)row0 * N + colb + poff]       = w0;
                *(float2*)&C[(size_t)(row0 + 8) * N + colb + poff] = w1;
            } else {
                *(float2*)&C[(size_t)row0 * N + colb + tg * 2]
                    = make_float2(v00, v01);
                *(float2*)&C[(size_t)(row0 + 8) * N + colb + tg * 2]
                    = make_float2(v10, v11);
            }
        }
    }
}

// ---------------------------------------------------------------------------
// Flash attention, tf32, head-dim-permuted qkv (PROVEN R12, verbatim).
// Grid: (S/64, B*H). Block: 128. BQ=64, BK=32 dbuf cp.async.
// ---------------------------------------------------------------------------
#define OFF_K   0
#define OFF_V   4608
#define OFF_P   9216
#define SM_FLT  11776        // 47104 bytes

__global__ __launch_bounds__(128) void attn_tf32(
    const float* __restrict__ qkv, float* __restrict__ outp)
{
    __shared__ __align__(16) float smf[SM_FLT];

    const int tid  = threadIdx.x;
    const int warp = tid >> 5;
    const int lane = tid & 31;
    const int g    = lane >> 2;
    const int tg   = lane & 3;
    const int wq0  = warp * 16;

    const int qt = blockIdx.x;
    const int bh = blockIdx.y;
    const int b  = bh >> 4;
    const int h  = bh & 15;

    const size_t rowbase = (size_t)b * SEQ * QKVN;
    const int qcol = h * DHEAD;
    const int kcol = DMODEL + h * DHEAD;
    const int vcol = 2 * DMODEL + h * DHEAD;
    const int q0   = qt * 64;

#pragma unroll
    for (int i = 0; i < 8; i++) {
        int f  = i * 128 + tid;
        int r  = f >> 4;
        int c4 = (f & 15) << 2;
        cp16(&smf[r * 72 + c4],
             &qkv[rowbase + (size_t)(q0 + r) * QKVN + qcol + c4]);
    }
    CP_COMMIT();
    CP_WAIT0();
    __syncthreads();

    unsigned qa[8][4];
    {
        const float2* Q2 = (const float2*)smf;
#pragma unroll
        for (int ks = 0; ks < 8; ks++) {
            float2 p = Q2[(wq0 + g    ) * 36 + ks * 4 + tg];
            float2 q = Q2[(wq0 + g + 8) * 36 + ks * 4 + tg];
            qa[ks][0] = __float_as_uint(p.x);
            qa[ks][1] = __float_as_uint(q.x);
            qa[ks][2] = __float_as_uint(p.y);
            qa[ks][3] = __float_as_uint(q.y);
        }
    }
    __syncthreads();

    float o[8][4];
#pragma unroll
    for (int i = 0; i < 8; i++)
#pragma unroll
        for (int j = 0; j < 4; j++) o[i][j] = 0.f;
    float mx0 = -INFINITY, mx1 = -INFINITY;
    float l0 = 0.f, l1 = 0.f;

    const int pe0 = (tg < 2) ? tg * 4     : tg * 4 - 7;
    const int pe1 = (tg < 2) ? tg * 4 + 2 : tg * 4 - 5;

#define ATT_ISSUE(nb, k0g)                                                     \
    {                                                                          \
        _Pragma("unroll")                                                      \
        for (int i = 0; i < 4; i++) {                                          \
            int f  = i * 128 + tid;                                            \
            int r  = f >> 4;                                                   \
            int c4 = (f & 15) << 2;                                            \
            cp16(&smf[OFF_K + (nb) * 2304 + r * 72 + c4],                      \
                 &qkv[rowbase + (size_t)((k0g) + r) * QKVN + kcol + c4]);      \
            cp16(&smf[OFF_V + (nb) * 2304 + r * 72 + c4],                      \
                 &qkv[rowbase + (size_t)((k0g) + r) * QKVN + vcol + c4]);      \
        }                                                                      \
        CP_COMMIT();                                                           \
    }

    ATT_ISSUE(0, 0)

    const int NT = SEQ / 32;
    for (int t = 0; t < NT; t++) {
        const int buf = t & 1;

        if (t + 1 < NT) {
            ATT_ISSUE(buf ^ 1, (t + 1) * 32)
            CP_WAIT1();
        } else {
            CP_WAIT0();
        }
        __syncthreads();

        const float2* K2 = (const float2*)(smf + OFF_K + buf * 2304);
        const float*  Vs = smf + OFF_V + buf * 2304;

        float s[4][4];
#pragma unroll
        for (int na = 0; na < 4; na++)
#pragma unroll
            for (int r = 0; r < 4; r++) s[na][r] = 0.f;

#pragma unroll
        for (int ks = 0; ks < 8; ks++) {
            const int kk2 = ks * 4;
#pragma unroll
            for (int na = 0; na < 4; na++) {
                float2 bb = K2[(na * 8 + g) * 36 + kk2 + tg];
                mma8(s[na], qa[ks][0], qa[ks][1], qa[ks][2], qa[ks][3],
                     __float_as_uint(bb.x), __float_as_uint(bb.y));
            }
        }

        float t0 = -INFINITY, t1 = -INFINITY;
#pragma unroll
        for (int na = 0; na < 4; na++) {
            s[na][0] *= 0.125f; s[na][1] *= 0.125f;
            s[na][2] *= 0.125f; s[na][3] *= 0.125f;
            t0 = fmaxf(t0, fmaxf(s[na][0], s[na][1]));
            t1 = fmaxf(t1, fmaxf(s[na][2], s[na][3]));
        }
        t0 = fmaxf(t0, __shfl_xor_sync(0xffffffffu, t0, 1));
        t0 = fmaxf(t0, __shfl_xor_sync(0xffffffffu, t0, 2));
        t1 = fmaxf(t1, __shfl_xor_sync(0xffffffffu, t1, 1));
        t1 = fmaxf(t1, __shfl_xor_sync(0xffffffffu, t1, 2));

        float mn0 = fmaxf(mx0, t0), mn1 = fmaxf(mx1, t1);
        float corr0 = __expf(mx0 - mn0), corr1 = __expf(mx1 - mn1);

        float ls0 = 0.f, ls1 = 0.f;
        {
            float* Pr0 = smf + OFF_P + (wq0 + g    ) * 40;
            float* Pr1 = smf + OFF_P + (wq0 + g + 8) * 40;
#pragma unroll
            for (int na = 0; na < 4; na++) {
                float p0 = __expf(s[na][0] - mn0);
                float p1 = __expf(s[na][1] - mn0);
                float p2 = __expf(s[na][2] - mn1);
                float p3 = __expf(s[na][3] - mn1);
                ls0 += p0 + p1; ls1 += p2 + p3;
                int cb = na * 8;
                Pr0[cb + pe0] = roundtf(p0); Pr0[cb + pe1] = roundtf(p1);
                Pr1[cb + pe0] = roundtf(p2); Pr1[cb + pe1] = roundtf(p3);
            }
        }
        ls0 += __shfl_xor_sync(0xffffffffu, ls0, 1);
        ls0 += __shfl_xor_sync(0xffffffffu, ls0, 2);
        ls1 += __shfl_xor_sync(0xffffffffu, ls1, 1);
        ls1 += __shfl_xor_sync(0xffffffffu, ls1, 2);
        l0 = l0 * corr0 + ls0;  mx0 = mn0;
        l1 = l1 * corr1 + ls1;  mx1 = mn1;

#pragma unroll
        for (int na = 0; na < 8; na++) {
            o[na][0] *= corr0; o[na][1] *= corr0;
            o[na][2] *= corr1; o[na][3] *= corr1;
        }

        __syncwarp();

        {
            const float2* P2 = (const float2*)(smf + OFF_P);
#pragma unroll
            for (int ks = 0; ks < 4; ks++) {
                const int kk = ks * 8;
                float2 pa = P2[(wq0 + g    ) * 20 + ks * 4 + tg];
                float2 pb = P2[(wq0 + g + 8) * 20 + ks * 4 + tg];
                unsigned a0 = __float_as_uint(pa.x);
                unsigned a1 = __float_as_uint(pb.x);
                unsigned a2 = __float_as_uint(pa.y);
                unsigned a3 = __float_as_uint(pb.y);
#pragma unroll
                for (int na = 0; na < 8; na++) {
                    int n = na * 8 + g;
                    unsigned b0 = __float_as_uint(Vs[(kk + tg    ) * 72 + n]);
                    unsigned b1 = __float_as_uint(Vs[(kk + tg + 4) * 72 + n]);
                    mma8(o[na], a0, a1, a2, a3, b0, b1);
                }
            }
        }
        __syncthreads();
    }

    float inv0 = 1.0f / l0, inv1 = 1.0f / l1;
    int row0 = q0 + wq0 + g;
    size_t base0 = ((size_t)bh * SEQ + row0)     * DHEAD;
    size_t base1 = ((size_t)bh * SEQ + row0 + 8) * DHEAD;
#pragma unroll
    for (int na = 0; na < 8; na++) {
        int c = na * 8 + tg * 2;
        float2 v0 = { roundtf(o[na][0] * inv0), roundtf(o[na][1] * inv0) };
        float2 v1 = { roundtf(o[na][2] * inv1), roundtf(o[na][3] * inv1) };
        *(float2*)&outp[base0 + c] = v0;
        *(float2*)&outp[base1 + c] = v1;
    }
}

// ---------------------------------------------------------------------------
// Launch
// ---------------------------------------------------------------------------
extern "C" void kernel_launch(void* const* d_in, const int* in_sizes, int n_in,
                              void* d_out, int out_size)
{
    const float* x     = (const float*)d_in[0];
    const float* w_in  = (const float*)d_in[1];
    const float* b_in  = (const float*)d_in[2];
    const float* w_out = (const float*)d_in[3];
    const float* b_out = (const float*)d_in[4];
    float* out = (float*)d_out;

    float *qkv_p, *att_p, *xr_p, *wir_p, *wor_p;
    cudaGetSymbolAddress((void**)&qkv_p, g_qkv);
    cudaGetSymbolAddress((void**)&att_p, g_att);
    cudaGetSymbolAddress((void**)&xr_p,  g_xr);
    cudaGetSymbolAddress((void**)&wir_p, g_wir);
    cudaGetSymbolAddress((void**)&wor_p, g_wor);

    cudaFuncSetAttribute(gemm_tf32<1>,
        cudaFuncAttributeMaxDynamicSharedMemorySize, GEMM_SMEM);
    cudaFuncSetAttribute(gemm_tf32<0>,
        cudaFuncAttributeMaxDynamicSharedMemorySize, GEMM_SMEM);

    // 0) Fused round + k-permute for all three inputs (single launch)
    round_perm_all<<<(N8_TOT + 255) / 256, 256>>>(x, w_in, w_out,
                                                  xr_p, wir_p, wor_p);
    // 1) QKV = x @ w_in^T + b_in  (MODE=1: rounded + sigma-permuted, STG.64)
    {
        dim3 grid(QKVN / 128, MROWS / 128);
        gemm_tf32<1><<<grid, 128, GEMM_SMEM>>>(xr_p, wir_p, b_in, qkv_p,
                                               MROWS, QKVN, DMODEL);
    }
    // 2) attention (permuted-dim qkv) -> g_att (permuted) in [B][H][S][Dh]
    {
        dim3 grid(SEQ / 64, BATCH * NHEADS);
        attn_tf32<<<grid, 128>>>(qkv_p, att_p);
    }
    // 3) out = att @ w_out^T + b_out (MODE=0: natural fp32 output)
    {
        dim3 grid(DMODEL / 128, MROWS / 128);
        gemm_tf32<0><<<grid, 128, GEMM_SMEM>>>(att_p, wor_p, b_out, out,
                                               MROWS, DMODEL, DMODEL);
    }
}